// round 16
// baseline (speedup 1.0000x reference)
#include <cuda_runtime.h>
#include <cuda_fp16.h>
#include <cstdint>

// ---------------- problem / tile constants ----------------
#define MB      8192
#define NGATE   1024
#define BM      128          // CTA M tile
#define NJ      64           // gate-local cols per CTA (virtual N = 256)
#define NKT     32           // 2048 halves / 64 per stage
#define STAGES  3
#define THREADS 512

#define A_STAGE_BYTES 16384                       // 128 rows x 128 B
#define B_STAGE_BYTES 32768                       // 256 vrows x 128 B
#define STAGE_BYTES   (A_STAGE_BYTES + B_STAGE_BYTES)   // 48 KB
#define SMEM_DYN      (STAGES * STAGE_BYTES)      // 147456 B

// fp16 scratch in PANEL layout (SW128 pre-swizzled):
//   A panels 16 KB: p = mt*32 + kt (mt 0..63, kt 0..31); rows mt*128..+127, halves kt*64..+63
//   B panels 32 KB: q = jt*32 + kt (jt 0..15); vrow r = g*64+l -> W row g*1024 + jt*64 + l
// A region [0, 32 MB), B region [32 MB, 48 MB).
#define A_REGION_BYTES 33554432u
__device__ __align__(16) __half g_fp16[25165824];

// ---------------- helpers ----------------
__device__ __forceinline__ uint32_t smem_u32(const void* p) {
    return (uint32_t)__cvta_generic_to_shared(p);
}
__device__ __forceinline__ uint32_t sw128(uint32_t off) {
    return off ^ ((off >> 3) & 0x70);
}
__device__ __forceinline__ uint32_t h2_bits(__half2 h) {
    return *reinterpret_cast<const uint32_t*>(&h);
}
__device__ __forceinline__ void cp16(uint32_t dst, const void* src) {
    asm volatile("cp.async.cg.shared.global [%0], [%1], 16;\n" :: "r"(dst), "l"(src));
}
__device__ __forceinline__ void cp_commit() { asm volatile("cp.async.commit_group;\n"); }
template <int N>
__device__ __forceinline__ void cp_wait() {
    asm volatile("cp.async.wait_group %0;\n" :: "n"(N));
}
__device__ __forceinline__ void ldsm_x4(uint32_t* r, uint32_t addr) {
    asm volatile("ldmatrix.sync.aligned.m8n8.x4.shared.b16 {%0,%1,%2,%3}, [%4];"
                 : "=r"(r[0]), "=r"(r[1]), "=r"(r[2]), "=r"(r[3]) : "r"(addr));
}
__device__ __forceinline__ void ldsm_x2(uint32_t* r, uint32_t addr) {
    asm volatile("ldmatrix.sync.aligned.m8n8.x2.shared.b16 {%0,%1}, [%2];"
                 : "=r"(r[0]), "=r"(r[1]) : "r"(addr));
}
__device__ __forceinline__ void mma_f16(float* d, const uint32_t* a, const uint32_t* b) {
    asm volatile(
        "mma.sync.aligned.m16n8k16.row.col.f32.f16.f16.f32 "
        "{%0,%1,%2,%3}, {%4,%5,%6,%7}, {%8,%9}, {%0,%1,%2,%3};"
        : "+f"(d[0]), "+f"(d[1]), "+f"(d[2]), "+f"(d[3])
        : "r"(a[0]), "r"(a[1]), "r"(a[2]), "r"(a[3]), "r"(b[0]), "r"(b[1]));
}
__device__ __forceinline__ float tanh_fast(float x) {
    float y;
    asm("tanh.approx.f32 %0, %1;" : "=f"(y) : "f"(x));
    return y;
}
__device__ __forceinline__ float sigmoid_fast(float x) {
    return 0.5f * tanh_fast(0.5f * x) + 0.5f;
}

// ---------------- fp32 -> fp16 panel-layout conversion ----------------
// 16-byte output chunk per step; 3M chunks (A: 2M, B: 1M).
__global__ void __launch_bounds__(256, 8)
convert_panels_kernel(const float* __restrict__ e_t, const float* __restrict__ h_prev,
                      const float* __restrict__ W_x, const float* __restrict__ W_h) {
    const int NCH = 3 * 1024 * 1024;
    const int stride = gridDim.x * blockDim.x;
    char* const dst0 = reinterpret_cast<char*>(g_fp16);
    for (int t = blockIdx.x * blockDim.x + threadIdx.x; t < NCH; t += stride) {
        const float* srcp;
        size_t dst_byte;
        if (t < 2097152) {                       // A chunk (16 KB panels, 1024 chunks each)
            const int p = t >> 10, u = t & 1023, r = u >> 3, c = u & 7;
            const int mt = p >> 5, kt = p & 31;
            const float* s = (kt < 16) ? e_t : h_prev;
            const int kloc = (kt & 15) * 64;
            srcp = s + (size_t)(mt * 128 + r) * 1024 + kloc + c * 8;
            dst_byte = (size_t)p * 16384 + sw128((uint32_t)(r * 128 + c * 16));
        } else {                                 // B chunk (32 KB panels, 2048 chunks each)
            const int tt = t - 2097152;
            const int q = tt >> 11, u = tt & 2047, r = u >> 3, c = u & 7;
            const int jt = q >> 5, kt = q & 31;
            const float* s = (kt < 16) ? W_x : W_h;
            const int kloc = (kt & 15) * 64;
            const int g = r >> 6, l = r & 63;
            srcp = s + (size_t)(g * 1024 + jt * 64 + l) * 1024 + kloc + c * 8;
            dst_byte = (size_t)A_REGION_BYTES + (size_t)q * 32768
                     + sw128((uint32_t)(r * 128 + c * 16));
        }
        const float4 v0 = reinterpret_cast<const float4*>(srcp)[0];
        const float4 v1 = reinterpret_cast<const float4*>(srcp)[1];
        uint4 o;
        o.x = h2_bits(__floats2half2_rn(v0.x, v0.y));
        o.y = h2_bits(__floats2half2_rn(v0.z, v0.w));
        o.z = h2_bits(__floats2half2_rn(v1.x, v1.y));
        o.w = h2_bits(__floats2half2_rn(v1.z, v1.w));
        *reinterpret_cast<uint4*>(dst0 + dst_byte) = o;
    }
}

// ---------------- main fused LSTM kernel ----------------
// CTA: 128 rows x 64 gate-local cols (virtual 128x256). 16 warps, grid 2m x 8n;
// per-warp tile 64 rows x 8 gate-local cols of all 4 gates (= R13's proven shape).
// Loader: linear panel copy (src offset == dst offset), cp.async.cg.
__global__ void __launch_bounds__(THREADS, 1)
lstm_mma_kernel(const float* __restrict__ c_prev,
                const float* __restrict__ b_x,
                const float* __restrict__ b_h,
                const float* __restrict__ b_extra,
                float* __restrict__ out)
{
    extern __shared__ char smb[];

    const int tid  = threadIdx.x;
    const int warp = tid >> 5;
    const int lane = tid & 31;
    const int gid  = lane >> 2;
    const int tg   = lane & 3;
    const int wm   = warp >> 3;     // 0..1 -> rows wm*64
    const int wn   = warp & 7;      // 0..7 -> gate-local cols wn*8
    const int m0   = blockIdx.y * BM;
    const int j0   = blockIdx.x * NJ;

    const char* const Apan = reinterpret_cast<const char*>(g_fp16)
                           + (size_t)blockIdx.y * 524288;           // 32 x 16 KB
    const char* const Bpan = reinterpret_cast<const char*>(g_fp16)
                           + A_REGION_BYTES + (size_t)blockIdx.x * 1048576;  // 32 x 32 KB

    auto load_stage = [&](int kt, int stg) {
        const uint32_t As = smem_u32(smb) + (uint32_t)(stg * STAGE_BYTES);
        const uint32_t Bs = As + A_STAGE_BYTES;
        const char* asrc = Apan + (size_t)kt * 16384;
        const char* bsrc = Bpan + (size_t)kt * 32768;
        #pragma unroll
        for (int i = 0; i < 2; i++) {           // A: 1024 chunks / 512 threads
            const uint32_t off = (uint32_t)(tid * 16 + i * 8192);
            cp16(As + off, asrc + off);
        }
        #pragma unroll
        for (int i = 0; i < 4; i++) {           // B: 2048 chunks / 512 threads
            const uint32_t off = (uint32_t)(tid * 16 + i * 8192);
            cp16(Bs + off, bsrc + off);
        }
    };

    float acc[4][4][4];   // [m_frag][gate][elem]
    #pragma unroll
    for (int i = 0; i < 4; i++)
        #pragma unroll
        for (int g = 0; g < 4; g++)
            #pragma unroll
            for (int e = 0; e < 4; e++) acc[i][g][e] = 0.0f;

    load_stage(0, 0); cp_commit();
    load_stage(1, 1); cp_commit();

    // ---- per-lane ldmatrix base addresses (stage-relative, bytes) ----
    uint32_t a_base[4];
    {
        const int tilesel = lane >> 3;
        const int rin     = lane & 7;
        const int radd    = (tilesel & 1) ? 8 : 0;
        const uint32_t kofs = (tilesel >= 2) ? 16u : 0u;
        const uint32_t key  = (uint32_t)rin << 4;
        #pragma unroll
        for (int i = 0; i < 4; i++) {
            const int trow = wm * 64 + i * 16 + radd + rin;
            a_base[i] = (uint32_t)(trow * 128) + (kofs ^ key);
        }
    }
    uint32_t b_base[4];
    {
        const int rin  = lane & 7;
        const uint32_t kofs = ((lane >> 3) & 1) ? 16u : 0u;
        const uint32_t key  = (uint32_t)rin << 4;
        #pragma unroll
        for (int g = 0; g < 4; g++) {
            const int nrow = g * 64 + wn * 8 + rin;     // B tile: 256 vrows
            b_base[g] = (uint32_t)(nrow * 128) + (kofs ^ key);
        }
    }

    for (int kt = 0; kt < NKT; kt++) {
        if (kt + 1 < NKT) cp_wait<1>(); else cp_wait<0>();
        __syncthreads();    // stage kt visible; stage (kt+2)%3 reads (iter kt-1) retired

        if (kt + 2 < NKT) {
            load_stage(kt + 2, (kt + 2) % STAGES);
            cp_commit();
        }

        const uint32_t As = smem_u32(smb) + (uint32_t)((kt % STAGES) * STAGE_BYTES);
        const uint32_t Bs = As + A_STAGE_BYTES;

        #pragma unroll
        for (int ks = 0; ks < 4; ks++) {
            const uint32_t kx = (uint32_t)(ks * 32);
            uint32_t a[4][4], b[4][2];
            #pragma unroll
            for (int i = 0; i < 4; i++)
                ldsm_x4(a[i], (As + a_base[i]) ^ kx);
            #pragma unroll
            for (int g = 0; g < 4; g++)
                ldsm_x2(b[g], (Bs + b_base[g]) ^ kx);
            #pragma unroll
            for (int i = 0; i < 4; i++)
                #pragma unroll
                for (int g = 0; g < 4; g++)
                    mma_f16(acc[i][g], a[i], b[g]);
        }
    }

    // ---- fused epilogue (registers only) ----
    const int jg = j0 + wn * 8 + tg * 2;
    float bsum[4][2];
    #pragma unroll
    for (int g = 0; g < 4; g++)
        #pragma unroll
        for (int c = 0; c < 2; c++) {
            const int idx = g * NGATE + jg + c;
            bsum[g][c] = b_x[idx] + b_h[idx] + b_extra[idx];
        }

    #pragma unroll
    for (int i = 0; i < 4; i++) {
        #pragma unroll
        for (int h = 0; h < 2; h++) {
            const int mg = m0 + wm * 64 + i * 16 + gid + h * 8;
            const float2 cp = *reinterpret_cast<const float2*>(
                c_prev + (size_t)mg * 1024 + jg);
            float ht[2], ct[2];
            #pragma unroll
            for (int c = 0; c < 2; c++) {
                const int e = h * 2 + c;
                const float fg = sigmoid_fast(acc[i][0][e] + bsum[0][c]);
                const float ig = sigmoid_fast(acc[i][1][e] + bsum[1][c]);
                const float og = sigmoid_fast(acc[i][2][e] + bsum[2][c]);
                const float cc = tanh_fast   (acc[i][3][e] + bsum[3][c]);
                const float cpv = (c == 0) ? cp.x : cp.y;
                ct[c] = fg * cpv + ig * cc;
                ht[c] = og * tanh_fast(ct[c]);
            }
            *reinterpret_cast<float2*>(out + (size_t)mg * 1024 + jg) =
                make_float2(ht[0], ht[1]);
            *reinterpret_cast<float2*>(
                out + (size_t)MB * 1024 + (size_t)mg * 1024 + jg) =
                make_float2(ct[0], ct[1]);
        }
    }
}

// ---------------- launch ----------------
extern "C" void kernel_launch(void* const* d_in, const int* in_sizes, int n_in,
                              void* d_out, int out_size) {
    const float* e_t     = (const float*)d_in[0];
    const float* h_prev  = (const float*)d_in[1];
    const float* c_prev  = (const float*)d_in[2];
    const float* W_x     = (const float*)d_in[3];
    const float* b_x     = (const float*)d_in[4];
    const float* W_h     = (const float*)d_in[5];
    const float* b_h     = (const float*)d_in[6];
    const float* b_extra = (const float*)d_in[7];
    float* out = (float*)d_out;

    cudaFuncSetAttribute(lstm_mma_kernel,
                         cudaFuncAttributeMaxDynamicSharedMemorySize, SMEM_DYN);

    convert_panels_kernel<<<4736, 256>>>(e_t, h_prev, W_x, W_h);

    dim3 grid(NGATE / NJ, MB / BM);   // (16, 64)
    lstm_mma_kernel<<<grid, THREADS, SMEM_DYN>>>(
        c_prev, b_x, b_h, b_extra, out);
}

// round 17
// speedup vs baseline: 1.1213x; 1.1213x over previous
#include <cuda_runtime.h>
#include <cuda_fp16.h>
#include <cstdint>

// ---------------- problem / tile constants ----------------
#define MB      8192
#define NGATE   1024
#define BM      128          // CTA M tile
#define NJ      32           // gate-local cols per CTA (virtual N = 128)
#define NKT     32           // 2048 halves / 64 per stage
#define STAGES  3
#define THREADS 256

#define A_STAGE_BYTES 16384                       // 128 rows x 128 B
#define B_STAGE_BYTES 16384                       // 128 vrows x 128 B
#define STAGE_BYTES   (A_STAGE_BYTES + B_STAGE_BYTES)   // 32 KB
#define SMEM_DYN      (STAGES * STAGE_BYTES)      // 98304 B

// fp16 scratch in PANEL layout (16 KB SW128 pre-swizzled panels):
//   A panels: p = mt*32 + kt (mt 0..63): rows mt*128..+127, halves kt*64..+63
//   B panels: q = jt*32 + kt (jt 0..31): vrow r = g*32+l -> W row g*1024 + jt*32 + l
// A region [0, 32 MB), B region [32 MB, 48 MB).
#define A_REGION_BYTES 33554432u
__device__ __align__(16) __half g_fp16[25165824];

// ---------------- helpers ----------------
__device__ __forceinline__ uint32_t smem_u32(const void* p) {
    return (uint32_t)__cvta_generic_to_shared(p);
}
__device__ __forceinline__ uint32_t sw128(uint32_t off) {
    return off ^ ((off >> 3) & 0x70);
}
__device__ __forceinline__ uint32_t h2_bits(__half2 h) {
    return *reinterpret_cast<const uint32_t*>(&h);
}
__device__ __forceinline__ void cp16(uint32_t dst, const void* src) {
    asm volatile("cp.async.cg.shared.global [%0], [%1], 16;\n" :: "r"(dst), "l"(src));
}
__device__ __forceinline__ void cp_commit() { asm volatile("cp.async.commit_group;\n"); }
template <int N>
__device__ __forceinline__ void cp_wait() {
    asm volatile("cp.async.wait_group %0;\n" :: "n"(N));
}
__device__ __forceinline__ void ldsm_x4(uint32_t* r, uint32_t addr) {
    asm volatile("ldmatrix.sync.aligned.m8n8.x4.shared.b16 {%0,%1,%2,%3}, [%4];"
                 : "=r"(r[0]), "=r"(r[1]), "=r"(r[2]), "=r"(r[3]) : "r"(addr));
}
__device__ __forceinline__ void mma_f16(float* d, const uint32_t* a, const uint32_t* b) {
    asm volatile(
        "mma.sync.aligned.m16n8k16.row.col.f32.f16.f16.f32 "
        "{%0,%1,%2,%3}, {%4,%5,%6,%7}, {%8,%9}, {%0,%1,%2,%3};"
        : "+f"(d[0]), "+f"(d[1]), "+f"(d[2]), "+f"(d[3])
        : "r"(a[0]), "r"(a[1]), "r"(a[2]), "r"(a[3]), "r"(b[0]), "r"(b[1]));
}
__device__ __forceinline__ float tanh_fast(float x) {
    float y;
    asm("tanh.approx.f32 %0, %1;" : "=f"(y) : "f"(x));
    return y;
}
__device__ __forceinline__ float sigmoid_fast(float x) {
    return 0.5f * tanh_fast(0.5f * x) + 0.5f;
}

// ---------------- fp32 -> fp16 panel-layout conversion ----------------
// 16-byte output chunk per step; 3M chunks (A: 2M, B: 1M). 16 KB panels both sides.
__global__ void __launch_bounds__(256, 8)
convert_panels_kernel(const float* __restrict__ e_t, const float* __restrict__ h_prev,
                      const float* __restrict__ W_x, const float* __restrict__ W_h) {
    const int NCH = 3 * 1024 * 1024;
    const int stride = gridDim.x * blockDim.x;
    char* const dst0 = reinterpret_cast<char*>(g_fp16);
    for (int t = blockIdx.x * blockDim.x + threadIdx.x; t < NCH; t += stride) {
        const float* srcp;
        size_t dst_byte;
        if (t < 2097152) {                       // A chunk
            const int p = t >> 10, u = t & 1023, r = u >> 3, c = u & 7;
            const int mt = p >> 5, kt = p & 31;
            const float* s = (kt < 16) ? e_t : h_prev;
            const int kloc = (kt & 15) * 64;
            srcp = s + (size_t)(mt * 128 + r) * 1024 + kloc + c * 8;
            dst_byte = (size_t)p * 16384 + sw128((uint32_t)(r * 128 + c * 16));
        } else {                                 // B chunk
            const int tt = t - 2097152;
            const int q = tt >> 10, u = tt & 1023, r = u >> 3, c = u & 7;
            const int jt = q >> 5, kt = q & 31;
            const float* s = (kt < 16) ? W_x : W_h;
            const int kloc = (kt & 15) * 64;
            const int g = r >> 5, l = r & 31;
            srcp = s + (size_t)(g * 1024 + jt * 32 + l) * 1024 + kloc + c * 8;
            dst_byte = (size_t)A_REGION_BYTES + (size_t)q * 16384
                     + sw128((uint32_t)(r * 128 + c * 16));
        }
        const float4 v0 = reinterpret_cast<const float4*>(srcp)[0];
        const float4 v1 = reinterpret_cast<const float4*>(srcp)[1];
        uint4 o;
        o.x = h2_bits(__floats2half2_rn(v0.x, v0.y));
        o.y = h2_bits(__floats2half2_rn(v0.z, v0.w));
        o.z = h2_bits(__floats2half2_rn(v1.x, v1.y));
        o.w = h2_bits(__floats2half2_rn(v1.z, v1.w));
        *reinterpret_cast<uint4*>(dst0 + dst_byte) = o;
    }
}

// ---------------- main fused LSTM kernel ----------------
// R13 proven shape: 2 CTAs/SM x 256 thr; CTA 128 rows x 32 gate-local cols;
// warp grid 2m x 4n, warp tile 64 x 8 gate-local (32 virtual).
// Panel-linear loader + B fragments via gate-paired ldmatrix.x4.
__global__ void __launch_bounds__(THREADS, 2)
lstm_mma_kernel(const float* __restrict__ c_prev,
                const float* __restrict__ b_x,
                const float* __restrict__ b_h,
                const float* __restrict__ b_extra,
                float* __restrict__ out)
{
    extern __shared__ char smb[];

    const int tid  = threadIdx.x;
    const int warp = tid >> 5;
    const int lane = tid & 31;
    const int gid  = lane >> 2;
    const int tg   = lane & 3;
    const int wm   = warp >> 2;     // 0..1 -> rows wm*64
    const int wn   = warp & 3;      // 0..3 -> gate-local cols wn*8
    const int m0   = blockIdx.y * BM;
    const int j0   = blockIdx.x * NJ;

    const char* const Apan = reinterpret_cast<const char*>(g_fp16)
                           + (size_t)blockIdx.y * 524288;                  // 32 x 16 KB
    const char* const Bpan = reinterpret_cast<const char*>(g_fp16)
                           + A_REGION_BYTES + (size_t)blockIdx.x * 524288; // 32 x 16 KB

    auto load_stage = [&](int kt, int stg) {
        const uint32_t As = smem_u32(smb) + (uint32_t)(stg * STAGE_BYTES);
        const uint32_t Bs = As + A_STAGE_BYTES;
        const char* asrc = Apan + (size_t)kt * 16384;
        const char* bsrc = Bpan + (size_t)kt * 16384;
        #pragma unroll
        for (int i = 0; i < 4; i++) {           // A: 1024 chunks / 256 threads
            const uint32_t off = (uint32_t)(tid * 16 + i * 4096);
            cp16(As + off, asrc + off);
        }
        #pragma unroll
        for (int i = 0; i < 4; i++) {           // B: 1024 chunks / 256 threads
            const uint32_t off = (uint32_t)(tid * 16 + i * 4096);
            cp16(Bs + off, bsrc + off);
        }
    };

    float acc[4][4][4];   // [m_frag][gate][elem]
    #pragma unroll
    for (int i = 0; i < 4; i++)
        #pragma unroll
        for (int g = 0; g < 4; g++)
            #pragma unroll
            for (int e = 0; e < 4; e++) acc[i][g][e] = 0.0f;

    load_stage(0, 0); cp_commit();
    load_stage(1, 1); cp_commit();

    // ---- per-lane ldmatrix base addresses (stage-relative, bytes) ----
    // A (x4): tile0 (rows+0,k+0), tile1 (rows+8,k+0), tile2 (rows+0,k+8), tile3 (rows+8,k+8)
    uint32_t a_base[4];
    {
        const int tilesel = lane >> 3;
        const int rin     = lane & 7;
        const int radd    = (tilesel & 1) ? 8 : 0;
        const uint32_t kofs = (tilesel >= 2) ? 16u : 0u;
        const uint32_t key  = (uint32_t)rin << 4;
        #pragma unroll
        for (int i = 0; i < 4; i++) {
            const int trow = wm * 64 + i * 16 + radd + rin;
            a_base[i] = (uint32_t)(trow * 128) + (kofs ^ key);
        }
    }
    // B (x4, 2 gates per call): tile0 (gate+0,k+0), tile1 (gate+0,k+8),
    //                           tile2 (gate+1,k+0), tile3 (gate+1,k+8)
    uint32_t b_base[2];
    {
        const int tilesel = lane >> 3;
        const int rin     = lane & 7;
        const int gadd    = tilesel >> 1;                    // 0 or 1
        const uint32_t kofs = (tilesel & 1) ? 16u : 0u;
        const uint32_t key  = (uint32_t)rin << 4;
        #pragma unroll
        for (int j = 0; j < 2; j++) {
            const int nrow = (j * 2 + gadd) * 32 + wn * 8 + rin;
            b_base[j] = (uint32_t)(nrow * 128) + (kofs ^ key);
        }
    }

    for (int kt = 0; kt < NKT; kt++) {
        if (kt + 1 < NKT) cp_wait<1>(); else cp_wait<0>();
        __syncthreads();    // stage kt visible; stage (kt+2)%3 reads retired

        if (kt + 2 < NKT) {
            load_stage(kt + 2, (kt + 2) % STAGES);
            cp_commit();
        }

        const uint32_t As = smem_u32(smb) + (uint32_t)((kt % STAGES) * STAGE_BYTES);
        const uint32_t Bs = As + A_STAGE_BYTES;

        #pragma unroll
        for (int ks = 0; ks < 4; ks++) {
            const uint32_t kx = (uint32_t)(ks * 32);
            uint32_t a[4][4], b[2][4];
            #pragma unroll
            for (int i = 0; i < 4; i++)
                ldsm_x4(a[i], (As + a_base[i]) ^ kx);
            #pragma unroll
            for (int j = 0; j < 2; j++)
                ldsm_x4(b[j], (Bs + b_base[j]) ^ kx);
            // b[j] = {g(2j)k0, g(2j)k8, g(2j+1)k0, g(2j+1)k8}
            #pragma unroll
            for (int i = 0; i < 4; i++)
                #pragma unroll
                for (int g = 0; g < 4; g++)
                    mma_f16(acc[i][g], a[i], &b[g >> 1][(g & 1) * 2]);
        }
    }

    // ---- fused epilogue (registers only) ----
    const int jg = j0 + wn * 8 + tg * 2;
    float bsum[4][2];
    #pragma unroll
    for (int g = 0; g < 4; g++)
        #pragma unroll
        for (int c = 0; c < 2; c++) {
            const int idx = g * NGATE + jg + c;
            bsum[g][c] = b_x[idx] + b_h[idx] + b_extra[idx];
        }

    #pragma unroll
    for (int i = 0; i < 4; i++) {
        #pragma unroll
        for (int h = 0; h < 2; h++) {
            const int mg = m0 + wm * 64 + i * 16 + gid + h * 8;
            const float2 cp = *reinterpret_cast<const float2*>(
                c_prev + (size_t)mg * 1024 + jg);
            float ht[2], ct[2];
            #pragma unroll
            for (int c = 0; c < 2; c++) {
                const int e = h * 2 + c;
                const float fg = sigmoid_fast(acc[i][0][e] + bsum[0][c]);
                const float ig = sigmoid_fast(acc[i][1][e] + bsum[1][c]);
                const float og = sigmoid_fast(acc[i][2][e] + bsum[2][c]);
                const float cc = tanh_fast   (acc[i][3][e] + bsum[3][c]);
                const float cpv = (c == 0) ? cp.x : cp.y;
                ct[c] = fg * cpv + ig * cc;
                ht[c] = og * tanh_fast(ct[c]);
            }
            *reinterpret_cast<float2*>(out + (size_t)mg * 1024 + jg) =
                make_float2(ht[0], ht[1]);
            *reinterpret_cast<float2*>(
                out + (size_t)MB * 1024 + (size_t)mg * 1024 + jg) =
                make_float2(ct[0], ct[1]);
        }
    }
}

// ---------------- launch ----------------
extern "C" void kernel_launch(void* const* d_in, const int* in_sizes, int n_in,
                              void* d_out, int out_size) {
    const float* e_t     = (const float*)d_in[0];
    const float* h_prev  = (const float*)d_in[1];
    const float* c_prev  = (const float*)d_in[2];
    const float* W_x     = (const float*)d_in[3];
    const float* b_x     = (const float*)d_in[4];
    const float* W_h     = (const float*)d_in[5];
    const float* b_h     = (const float*)d_in[6];
    const float* b_extra = (const float*)d_in[7];
    float* out = (float*)d_out;

    cudaFuncSetAttribute(lstm_mma_kernel,
                         cudaFuncAttributeMaxDynamicSharedMemorySize, SMEM_DYN);

    convert_panels_kernel<<<4736, 256>>>(e_t, h_prev, W_x, W_h);

    dim3 grid(NGATE / NJ, MB / BM);   // (32, 64)
    lstm_mma_kernel<<<grid, THREADS, SMEM_DYN>>>(
        c_prev, b_x, b_h, b_extra, out);
}